// round 3
// baseline (speedup 1.0000x reference)
#include <cuda_runtime.h>
#include <math.h>

// Problem constants
#define BATCH   2
#define SEQ     2048
#define DMODEL  1024
#define HEADS   16
#define DHEAD   64
#define INNER   (HEADS*DHEAD)      // 1024
#define ROWS    (BATCH*SEQ)        // 4096
#define ATT_SCALE 0.125f           // 64^-0.5
#define MASK_NEG 1000000.0f

// Scratch (allocation-free rule: static __device__ globals)
__device__ float g_q[ROWS*INNER];
__device__ float g_k[ROWS*INNER];
__device__ float g_v[ROWS*INNER];
__device__ float g_o[ROWS*INNER];

// ---------------------------------------------------------------------------
// SGEMM: C[M,N] = A[M,K] * B[K,N'] (+bias), row-major.
// lda = K, ldc = N. B indexed as B[k*ldb + boff + n] (for Wkv column slicing).
// Block tile 128x128, BK=16, 256 threads, 8x8 per thread.
// ---------------------------------------------------------------------------
__global__ __launch_bounds__(256, 2)
void sgemm128(const float* __restrict__ A, const float* __restrict__ B,
              float* __restrict__ C, int M, int N, int K,
              int ldb, int boff, const float* __restrict__ bias)
{
    __shared__ float As[16][128];   // transposed: As[k][m]
    __shared__ float Bs[16][128];

    const int tid = threadIdx.x;
    const int tx  = tid & 15;       // 0..15 -> col group
    const int ty  = tid >> 4;       // 0..15 -> row group
    const int rowBase = blockIdx.y * 128;
    const int colBase = blockIdx.x * 128;

    float acc[8][8];
    #pragma unroll
    for (int i = 0; i < 8; i++)
        #pragma unroll
        for (int j = 0; j < 8; j++) acc[i][j] = 0.f;

    const int arow = tid >> 2;          // 0..63
    const int acol = (tid & 3) * 4;     // 0,4,8,12
    const int brow = tid >> 5;          // 0..7
    const int bcol = (tid & 31) * 4;    // 0..124

    for (int k0 = 0; k0 < K; k0 += 16) {
        // Load A tile (128 x 16), store transposed
        #pragma unroll
        for (int p = 0; p < 2; p++) {
            int r = arow + p * 64;
            float4 v = *(const float4*)(A + (long)(rowBase + r) * K + k0 + acol);
            As[acol + 0][r] = v.x;
            As[acol + 1][r] = v.y;
            As[acol + 2][r] = v.z;
            As[acol + 3][r] = v.w;
        }
        // Load B tile (16 x 128)
        #pragma unroll
        for (int p = 0; p < 2; p++) {
            int r = brow + p * 8;
            *(float4*)&Bs[r][bcol] =
                *(const float4*)(B + (long)(k0 + r) * ldb + boff + colBase + bcol);
        }
        __syncthreads();

        #pragma unroll
        for (int kk = 0; kk < 16; kk++) {
            float a[8], b[8];
            *(float4*)(a)     = *(const float4*)&As[kk][ty * 8];
            *(float4*)(a + 4) = *(const float4*)&As[kk][ty * 8 + 4];
            *(float4*)(b)     = *(const float4*)&Bs[kk][tx * 8];
            *(float4*)(b + 4) = *(const float4*)&Bs[kk][tx * 8 + 4];
            #pragma unroll
            for (int i = 0; i < 8; i++)
                #pragma unroll
                for (int j = 0; j < 8; j++)
                    acc[i][j] = fmaf(a[i], b[j], acc[i][j]);
        }
        __syncthreads();
    }

    // Epilogue
    #pragma unroll
    for (int i = 0; i < 8; i++) {
        int r = rowBase + ty * 8 + i;
        #pragma unroll
        for (int j = 0; j < 8; j += 4) {
            int cc = colBase + tx * 8 + j;
            float4 v;
            v.x = acc[i][j + 0];
            v.y = acc[i][j + 1];
            v.z = acc[i][j + 2];
            v.w = acc[i][j + 3];
            if (bias) {
                v.x += bias[cc + 0];
                v.y += bias[cc + 1];
                v.z += bias[cc + 2];
                v.w += bias[cc + 3];
            }
            *(float4*)(C + (long)r * N + cc) = v;
        }
    }
}

// ---------------------------------------------------------------------------
// Flash attention (fp32). Q/K/V stored as [B, SEQ, DMODEL] with head h at
// column offset h*64 (row stride DMODEL). Per block: 64 queries of one
// (b,h), streaming over all 2048 keys in tiles of 64.
//
// Mask handling: the reference subtracts (1-mask[b,n])*1e6 from the logits
// IN FP32. At |x|~1e6 the fp32 ulp is 0.0625, so the masked rows' logits are
// quantized to a 0.0625 grid before softmax; the subsequent max-subtraction
// is Sterbenz-exact, so the quantization is observable in the output. We
// reproduce it exactly: s = fl(fl(s*SCALE) - pen), then online-softmax on
// those values (all later subtractions are of nearby values -> exact).
// ---------------------------------------------------------------------------
__global__ __launch_bounds__(256, 3)
void flash_attn(const float* __restrict__ Q, const float* __restrict__ K,
                const float* __restrict__ V, const int* __restrict__ mask,
                float* __restrict__ O)
{
    __shared__ float Qs[64][64];   // [query][dd]
    __shared__ float Kt[64][64];   // transposed: [dd][key]
    __shared__ float Vs[64][64];   // [key][dd]
    __shared__ float Ps[64][64];   // [query][key]

    const int b  = blockIdx.z;
    const int h  = blockIdx.y;
    const int nb = blockIdx.x;
    const int n0 = nb * 64;

    const int tid = threadIdx.x;
    const int tx  = tid & 15;      // key/dd col group (4 cols)
    const int ty  = tid >> 4;      // query row group (4 rows)

    const long baseQ = (long)b * SEQ * DMODEL + (long)h * DHEAD;

    // Load Q tile: 64 rows x 64 cols = 1024 float4, 4 per thread
    #pragma unroll
    for (int p = 0; p < 4; p++) {
        int idx = tid + p * 256;
        int r = idx >> 4;            // 0..63
        int c = (idx & 15) * 4;      // 0..60
        *(float4*)&Qs[r][c] = *(const float4*)(Q + baseQ + (long)(n0 + r) * DMODEL + c);
    }

    // Per-query-row mask penalty (4 rows per thread)
    float pen[4];
    #pragma unroll
    for (int i = 0; i < 4; i++) {
        int m = mask[b * SEQ + n0 + ty * 4 + i];
        pen[i] = (1.0f - (float)m) * MASK_NEG;
    }

    float acc[4][4];
    float m_i[4], l_i[4];
    #pragma unroll
    for (int i = 0; i < 4; i++) {
        m_i[i] = -3e30f;
        l_i[i] = 0.f;
        #pragma unroll
        for (int j = 0; j < 4; j++) acc[i][j] = 0.f;
    }

    for (int mt = 0; mt < SEQ / 64; mt++) {
        const int m0 = mt * 64;
        // Load K (transposed) and V tiles
        #pragma unroll
        for (int p = 0; p < 4; p++) {
            int idx = tid + p * 256;
            int r = idx >> 4;
            int c = (idx & 15) * 4;
            float4 kv = *(const float4*)(K + baseQ + (long)(m0 + r) * DMODEL + c);
            Kt[c + 0][r] = kv.x;
            Kt[c + 1][r] = kv.y;
            Kt[c + 2][r] = kv.z;
            Kt[c + 3][r] = kv.w;
            *(float4*)&Vs[r][c] = *(const float4*)(V + baseQ + (long)(m0 + r) * DMODEL + c);
        }
        __syncthreads();

        // S = Q * K^T  (4x4 per thread, inner dim 64)
        float s[4][4];
        #pragma unroll
        for (int i = 0; i < 4; i++)
            #pragma unroll
            for (int j = 0; j < 4; j++) s[i][j] = 0.f;

        #pragma unroll 8
        for (int dd = 0; dd < 64; dd++) {
            float a[4], bb[4];
            #pragma unroll
            for (int i = 0; i < 4; i++) a[i] = Qs[ty * 4 + i][dd];
            *(float4*)bb = *(const float4*)&Kt[dd][tx * 4];
            #pragma unroll
            for (int i = 0; i < 4; i++)
                #pragma unroll
                for (int j = 0; j < 4; j++)
                    s[i][j] = fmaf(a[i], bb[j], s[i][j]);
        }

        // Online softmax update (row stats shared by the 16 tx lanes).
        // Apply scale then subtract mask penalty as two separate fp32
        // roundings -- bit-matches the reference.
        #pragma unroll
        for (int i = 0; i < 4; i++) {
            #pragma unroll
            for (int j = 0; j < 4; j++) {
                float t = s[i][j] * ATT_SCALE;   // fl(s*SCALE)
                s[i][j] = t - pen[i];            // fl(t - 1e6) : quantizes
            }
            float mloc = s[i][0];
            #pragma unroll
            for (int j = 1; j < 4; j++) mloc = fmaxf(mloc, s[i][j]);
            #pragma unroll
            for (int off = 8; off >= 1; off >>= 1)
                mloc = fmaxf(mloc, __shfl_xor_sync(0xffffffffu, mloc, off));
            float mnew = fmaxf(m_i[i], mloc);
            float alpha = __expf(m_i[i] - mnew);
            float lloc = 0.f;
            #pragma unroll
            for (int j = 0; j < 4; j++) {
                s[i][j] = __expf(s[i][j] - mnew);
                lloc += s[i][j];
            }
            #pragma unroll
            for (int off = 8; off >= 1; off >>= 1)
                lloc += __shfl_xor_sync(0xffffffffu, lloc, off);
            l_i[i] = l_i[i] * alpha + lloc;
            m_i[i] = mnew;
            #pragma unroll
            for (int j = 0; j < 4; j++) acc[i][j] *= alpha;
        }

        // Publish P
        #pragma unroll
        for (int i = 0; i < 4; i++)
            *(float4*)&Ps[ty * 4 + i][tx * 4] = *(float4*)s[i];
        __syncthreads();

        // O += P * V  (inner dim = 64 keys)
        #pragma unroll 8
        for (int c = 0; c < 64; c++) {
            float a[4], bb[4];
            #pragma unroll
            for (int i = 0; i < 4; i++) a[i] = Ps[ty * 4 + i][c];
            *(float4*)bb = *(const float4*)&Vs[c][tx * 4];
            #pragma unroll
            for (int i = 0; i < 4; i++)
                #pragma unroll
                for (int j = 0; j < 4; j++)
                    acc[i][j] = fmaf(a[i], bb[j], acc[i][j]);
        }
        __syncthreads();
    }

    // Normalize and store
    #pragma unroll
    for (int i = 0; i < 4; i++) {
        float inv = 1.f / l_i[i];
        float4 v;
        v.x = acc[i][0] * inv;
        v.y = acc[i][1] * inv;
        v.z = acc[i][2] * inv;
        v.w = acc[i][3] * inv;
        *(float4*)(O + baseQ + (long)(n0 + ty * 4 + i) * DMODEL + tx * 4) = v;
    }
}

// ---------------------------------------------------------------------------
// Launch
// ---------------------------------------------------------------------------
extern "C" void kernel_launch(void* const* d_in, const int* in_sizes, int n_in,
                              void* d_out, int out_size)
{
    const float* x       = (const float*)d_in[0];
    const float* context = (const float*)d_in[1];
    const int*   mask    = (const int*)d_in[2];
    const float* Wq      = (const float*)d_in[3];
    const float* Wkv     = (const float*)d_in[4];
    const float* Wout    = (const float*)d_in[5];
    const float* bout    = (const float*)d_in[6];
    float* out = (float*)d_out;

    float *q, *k, *v, *o;
    cudaGetSymbolAddress((void**)&q, g_q);
    cudaGetSymbolAddress((void**)&k, g_k);
    cudaGetSymbolAddress((void**)&v, g_v);
    cudaGetSymbolAddress((void**)&o, g_o);

    dim3 blk(256);
    dim3 grid_proj(INNER / 128, ROWS / 128);   // (8, 32)

    // q = x @ Wq
    sgemm128<<<grid_proj, blk>>>(x, Wq, q, ROWS, INNER, DMODEL, INNER, 0, nullptr);
    // k = context @ Wkv[:, :1024], v = context @ Wkv[:, 1024:]
    sgemm128<<<grid_proj, blk>>>(context, Wkv, k, ROWS, INNER, DMODEL, 2 * INNER, 0, nullptr);
    sgemm128<<<grid_proj, blk>>>(context, Wkv, v, ROWS, INNER, DMODEL, 2 * INNER, INNER, nullptr);

    // attention
    dim3 grid_attn(SEQ / 64, HEADS, BATCH);
    flash_attn<<<grid_attn, blk>>>(q, k, v, mask, o);

    // out = o @ Wout + bout
    sgemm128<<<grid_proj, blk>>>(o, Wout, out, ROWS, DMODEL, INNER, DMODEL, 0, bout);
}

// round 7
// speedup vs baseline: 1.1142x; 1.1142x over previous
#include <cuda_runtime.h>
#include <cuda_bf16.h>
#include <math.h>
#include <stdint.h>

// Problem constants
#define BATCH   2
#define SEQ     2048
#define DMODEL  1024
#define HEADS   16
#define DHEAD   64
#define INNER   (HEADS*DHEAD)      // 1024
#define ROWS    (BATCH*SEQ)        // 4096
#define ATT_SCALE 0.125f
#define MASK_NEG 1000000.0f

// Scratch (allocation-free rule: static __device__ globals)
__device__ float g_q[ROWS*INNER];
__device__ float g_k[ROWS*INNER];
__device__ float g_v[ROWS*INNER];
__device__ float g_o[ROWS*INNER];

// ---------------------------------------------------------------------------
// mma.sync helpers (compute_103-compatible; NO tcgen05 — the harness PTX
// target is compute_103 which rejects arch-specific instructions)
// ---------------------------------------------------------------------------
__device__ __forceinline__ void mma_tf32(float* d, const uint32_t* a,
                                         uint32_t b0, uint32_t b1)
{
    asm volatile(
        "mma.sync.aligned.m16n8k8.row.col.f32.tf32.tf32.f32 "
        "{%0,%1,%2,%3}, {%4,%5,%6,%7}, {%8,%9}, {%0,%1,%2,%3};"
        : "+f"(d[0]), "+f"(d[1]), "+f"(d[2]), "+f"(d[3])
        : "r"(a[0]), "r"(a[1]), "r"(a[2]), "r"(a[3]), "r"(b0), "r"(b1));
}

__device__ __forceinline__ void mma_bf16(float* d, const uint32_t* a,
                                         uint32_t b0, uint32_t b1)
{
    asm volatile(
        "mma.sync.aligned.m16n8k16.row.col.f32.bf16.bf16.f32 "
        "{%0,%1,%2,%3}, {%4,%5,%6,%7}, {%8,%9}, {%0,%1,%2,%3};"
        : "+f"(d[0]), "+f"(d[1]), "+f"(d[2]), "+f"(d[3])
        : "r"(a[0]), "r"(a[1]), "r"(a[2]), "r"(a[3]), "r"(b0), "r"(b1));
}

__device__ __forceinline__ uint32_t f2tf32(float x) {
    uint32_t r; asm("cvt.rna.tf32.f32 %0, %1;" : "=r"(r) : "f"(x)); return r;
}

// ---------------------------------------------------------------------------
// SGEMM (fp32, proven): C[M,N] = A[M,K] * B[K,N'] (+bias), row-major.
// q,k MUST be fp32-accurate: the reference's fp32 (logit - 1e6) quantizes
// masked-row logits to a 0.0625 grid; logit errors > ~1e-5 flip grid cells.
// ---------------------------------------------------------------------------
__global__ __launch_bounds__(256, 2)
void sgemm128(const float* __restrict__ A, const float* __restrict__ B,
              float* __restrict__ C, int M, int N, int K,
              int ldb, int boff, const float* __restrict__ bias)
{
    __shared__ float As[16][128];   // transposed: As[k][m]
    __shared__ float Bs[16][128];

    const int tid = threadIdx.x;
    const int tx  = tid & 15;
    const int ty  = tid >> 4;
    const int rowBase = blockIdx.y * 128;
    const int colBase = blockIdx.x * 128;

    float acc[8][8];
    #pragma unroll
    for (int i = 0; i < 8; i++)
        #pragma unroll
        for (int j = 0; j < 8; j++) acc[i][j] = 0.f;

    const int arow = tid >> 2;
    const int acol = (tid & 3) * 4;
    const int brow = tid >> 5;
    const int bcol = (tid & 31) * 4;

    for (int k0 = 0; k0 < K; k0 += 16) {
        #pragma unroll
        for (int p = 0; p < 2; p++) {
            int r = arow + p * 64;
            float4 v = *(const float4*)(A + (long)(rowBase + r) * K + k0 + acol);
            As[acol + 0][r] = v.x;
            As[acol + 1][r] = v.y;
            As[acol + 2][r] = v.z;
            As[acol + 3][r] = v.w;
        }
        #pragma unroll
        for (int p = 0; p < 2; p++) {
            int r = brow + p * 8;
            *(float4*)&Bs[r][bcol] =
                *(const float4*)(B + (long)(k0 + r) * ldb + boff + colBase + bcol);
        }
        __syncthreads();

        #pragma unroll
        for (int kk = 0; kk < 16; kk++) {
            float a[8], b[8];
            *(float4*)(a)     = *(const float4*)&As[kk][ty * 8];
            *(float4*)(a + 4) = *(const float4*)&As[kk][ty * 8 + 4];
            *(float4*)(b)     = *(const float4*)&Bs[kk][tx * 8];
            *(float4*)(b + 4) = *(const float4*)&Bs[kk][tx * 8 + 4];
            #pragma unroll
            for (int i = 0; i < 8; i++)
                #pragma unroll
                for (int j = 0; j < 8; j++)
                    acc[i][j] = fmaf(a[i], b[j], acc[i][j]);
        }
        __syncthreads();
    }

    #pragma unroll
    for (int i = 0; i < 8; i++) {
        int r = rowBase + ty * 8 + i;
        #pragma unroll
        for (int j = 0; j < 8; j += 4) {
            int cc = colBase + tx * 8 + j;
            float4 v;
            v.x = acc[i][j + 0];
            v.y = acc[i][j + 1];
            v.z = acc[i][j + 2];
            v.w = acc[i][j + 3];
            if (bias) {
                v.x += bias[cc + 0];
                v.y += bias[cc + 1];
                v.z += bias[cc + 2];
                v.w += bias[cc + 3];
            }
            *(float4*)(C + (long)r * N + cc) = v;
        }
    }
}

// ---------------------------------------------------------------------------
// Flash attention on tensor cores (mma.sync).
//   QK: tf32 3-term split (qh*kh + ql*kh + qh*kl)  -> fp32-level logits
//   PV: bf16 3-term split (Ph*Vh + Pl*Vh + Ph*Vl)
// Block: 64 queries of one (b,h); 4 warps x 16 query rows; streams 32
// key-tiles of 64. Q fragments live in registers for the whole block;
// S-accumulator fragments re-pack directly into PV A-fragments (no smem
// round-trip for P). K stored transposed [d][key] as tf32 hi/lo; V stored
// transposed [d][key] as bf16 hi/lo.
// Mask: reproduce reference rounding s = fl(fl(dot*SCALE) - pen).
// ---------------------------------------------------------------------------
#define FLASH_SMEM (2*64*66*4 + 2*64*68*2)   // 51200 bytes

__global__ __launch_bounds__(128, 2)
void flash_mma(const float* __restrict__ Q, const float* __restrict__ K,
               const float* __restrict__ V, const int* __restrict__ mask,
               float* __restrict__ O)
{
    extern __shared__ char smem[];
    float* KtHi = (float*)smem;                              // [64][66]
    float* KtLo = KtHi + 64 * 66;                            // [64][66]
    __nv_bfloat16* VtHi = (__nv_bfloat16*)(KtLo + 64 * 66);  // [64][68]
    __nv_bfloat16* VtLo = VtHi + 64 * 68;                    // [64][68]

    const int b  = blockIdx.z;
    const int h  = blockIdx.y;
    const int n0 = blockIdx.x * 64;

    const int tid   = threadIdx.x;
    const int wid   = tid >> 5;
    const int lane  = tid & 31;
    const int r0    = wid * 16;          // warp's query-row base within tile
    const int row_a = lane >> 2;         // 0..7
    const int colc  = lane & 3;          // 0..3

    const long baseQ = (long)b * SEQ * DMODEL + (long)h * DHEAD;

    // ---- Q fragments (tf32 hi/lo), resident in registers ----
    // m16n8k8 A layout: a0=(r,k) a1=(r+8,k) a2=(r,k+4) a3=(r+8,k+4)
    uint32_t qh[32], ql[32];
    #pragma unroll
    for (int s = 0; s < 8; s++) {
        #pragma unroll
        for (int i = 0; i < 4; i++) {
            int rr = n0 + r0 + row_a + ((i & 1) << 3);
            int kk = (s << 3) + colc + ((i >> 1) << 2);
            float qv = Q[baseQ + (long)rr * DMODEL + kk];
            uint32_t hb = f2tf32(qv);
            qh[s*4 + i] = hb;
            ql[s*4 + i] = f2tf32(qv - __uint_as_float(hb));
        }
    }

    const float pen0 = (1.0f - (float)mask[b*SEQ + n0 + r0 + row_a])     * MASK_NEG;
    const float pen1 = (1.0f - (float)mask[b*SEQ + n0 + r0 + row_a + 8]) * MASK_NEG;

    float Oacc[32];
    #pragma unroll
    for (int i = 0; i < 32; i++) Oacc[i] = 0.f;
    float mstat[2] = {-1e30f, -1e30f};
    float lstat[2] = {0.f, 0.f};

    for (int kt = 0; kt < SEQ / 64; kt++) {
        const int m0 = kt * 64;
        __syncthreads();   // previous iteration's smem readers done
        // ---- load K,V tile, split + transpose into smem ----
        #pragma unroll
        for (int p = 0; p < 8; p++) {
            int idx = tid + p * 128;         // 0..1023
            int r = idx >> 4;                // key 0..63
            int c = (idx & 15) << 2;         // d
            float4 kv = *(const float4*)(K + baseQ + (long)(m0 + r) * DMODEL + c);
            float4 vv = *(const float4*)(V + baseQ + (long)(m0 + r) * DMODEL + c);
            float kf[4] = {kv.x, kv.y, kv.z, kv.w};
            float vf[4] = {vv.x, vv.y, vv.z, vv.w};
            #pragma unroll
            for (int i = 0; i < 4; i++) {
                uint32_t hb = f2tf32(kf[i]);
                KtHi[(c + i) * 66 + r] = __uint_as_float(hb);
                KtLo[(c + i) * 66 + r] =
                    __uint_as_float(f2tf32(kf[i] - __uint_as_float(hb)));
                __nv_bfloat16 vh = __float2bfloat16(vf[i]);
                VtHi[(c + i) * 68 + r] = vh;
                VtLo[(c + i) * 68 + r] =
                    __float2bfloat16(vf[i] - __bfloat162float(vh));
            }
        }
        __syncthreads();

        // ---- S = Q K^T (tf32 3-term), 8 n-tiles of 8 keys ----
        float S[32];
        #pragma unroll
        for (int i = 0; i < 32; i++) S[i] = 0.f;

        #pragma unroll
        for (int s = 0; s < 8; s++) {
            #pragma unroll
            for (int j = 0; j < 8; j++) {
                int krow = s * 8 + colc;
                int kcol = j * 8 + row_a;
                uint32_t bh0 = __float_as_uint(KtHi[krow * 66 + kcol]);
                uint32_t bh1 = __float_as_uint(KtHi[(krow + 4) * 66 + kcol]);
                uint32_t bl0 = __float_as_uint(KtLo[krow * 66 + kcol]);
                uint32_t bl1 = __float_as_uint(KtLo[(krow + 4) * 66 + kcol]);
                mma_tf32(&S[j*4], &qh[s*4], bh0, bh1);
                mma_tf32(&S[j*4], &ql[s*4], bh0, bh1);
                mma_tf32(&S[j*4], &qh[s*4], bl0, bl1);
            }
        }

        // ---- scale + mask (reference fp32 rounding) + online softmax ----
        // acc layout: c0=(r,2c) c1=(r,2c+1) c2=(r+8,2c) c3=(r+8,2c+1)
        #pragma unroll
        for (int t = 0; t < 2; t++) {
            float pent = t ? pen1 : pen0;
            float mloc = -1e30f;
            #pragma unroll
            for (int j = 0; j < 8; j++) {
                float v0 = S[j*4 + 2*t]     * ATT_SCALE - pent;
                float v1 = S[j*4 + 2*t + 1] * ATT_SCALE - pent;
                S[j*4 + 2*t]     = v0;
                S[j*4 + 2*t + 1] = v1;
                mloc = fmaxf(mloc, fmaxf(v0, v1));
            }
            mloc = fmaxf(mloc, __shfl_xor_sync(0xffffffffu, mloc, 1));
            mloc = fmaxf(mloc, __shfl_xor_sync(0xffffffffu, mloc, 2));
            float mnew  = fmaxf(mstat[t], mloc);
            float alpha = __expf(mstat[t] - mnew);
            float lloc = 0.f;
            #pragma unroll
            for (int j = 0; j < 8; j++) {
                float p0 = __expf(S[j*4 + 2*t]     - mnew);
                float p1 = __expf(S[j*4 + 2*t + 1] - mnew);
                S[j*4 + 2*t]     = p0;
                S[j*4 + 2*t + 1] = p1;
                lloc += p0 + p1;
            }
            lloc += __shfl_xor_sync(0xffffffffu, lloc, 1);
            lloc += __shfl_xor_sync(0xffffffffu, lloc, 2);
            lstat[t] = lstat[t] * alpha + lloc;
            mstat[t] = mnew;
            #pragma unroll
            for (int j = 0; j < 8; j++) {
                Oacc[j*4 + 2*t]     *= alpha;
                Oacc[j*4 + 2*t + 1] *= alpha;
            }
        }

        // ---- O += P V (bf16 3-term), P packed straight from S regs ----
        #pragma unroll
        for (int t2 = 0; t2 < 4; t2++) {
            // m16n8k16 A layout: a0=(r,k2c,2c+1) a1=(r+8,same) a2=(r,k+8) a3=(r+8,k+8)
            uint32_t ah[4], al[4];
            #pragma unroll
            for (int i = 0; i < 4; i++) {
                int jt  = 2*t2 + (i >> 1);       // S n-tile
                int off = (i & 1) * 2;           // 0: row r (c0,c1); 2: row r+8
                float p0 = S[jt*4 + off];
                float p1 = S[jt*4 + off + 1];
                __nv_bfloat16 h0 = __float2bfloat16(p0);
                __nv_bfloat16 h1 = __float2bfloat16(p1);
                ah[i] = ((uint32_t)__bfloat16_as_ushort(h1) << 16) |
                        (uint32_t)__bfloat16_as_ushort(h0);
                __nv_bfloat16 l0 = __float2bfloat16(p0 - __bfloat162float(h0));
                __nv_bfloat16 l1 = __float2bfloat16(p1 - __bfloat162float(h1));
                al[i] = ((uint32_t)__bfloat16_as_ushort(l1) << 16) |
                        (uint32_t)__bfloat16_as_ushort(l0);
            }
            #pragma unroll
            for (int j = 0; j < 8; j++) {
                int vrow = j * 8 + row_a;        // d index (n)
                int kk   = t2 * 16 + 2 * colc;   // key index (k)
                uint32_t bh0 = *(const uint32_t*)&VtHi[vrow * 68 + kk];
                uint32_t bh1 = *(const uint32_t*)&VtHi[vrow * 68 + kk + 8];
                uint32_t bl0 = *(const uint32_t*)&VtLo[vrow * 68 + kk];
                uint32_t bl1 = *(const uint32_t*)&VtLo[vrow * 68 + kk + 8];
                mma_bf16(&Oacc[j*4], ah, bh0, bh1);
                mma_bf16(&Oacc[j*4], al, bh0, bh1);
                mma_bf16(&Oacc[j*4], ah, bl0, bl1);
            }
        }
    }

    // ---- normalize + store ----
    float inv0 = 1.f / lstat[0];
    float inv1 = 1.f / lstat[1];
    int rowg = n0 + r0 + row_a;
    #pragma unroll
    for (int j = 0; j < 8; j++) {
        float2 v0 = make_float2(Oacc[j*4 + 0] * inv0, Oacc[j*4 + 1] * inv0);
        float2 v1 = make_float2(Oacc[j*4 + 2] * inv1, Oacc[j*4 + 3] * inv1);
        *(float2*)(O + baseQ + (long)rowg       * DMODEL + j*8 + 2*colc) = v0;
        *(float2*)(O + baseQ + (long)(rowg + 8) * DMODEL + j*8 + 2*colc) = v1;
    }
}

// ---------------------------------------------------------------------------
// Launch
// ---------------------------------------------------------------------------
extern "C" void kernel_launch(void* const* d_in, const int* in_sizes, int n_in,
                              void* d_out, int out_size)
{
    const float* x       = (const float*)d_in[0];
    const float* context = (const float*)d_in[1];
    const int*   mask    = (const int*)d_in[2];
    const float* Wq      = (const float*)d_in[3];
    const float* Wkv     = (const float*)d_in[4];
    const float* Wout    = (const float*)d_in[5];
    const float* bout    = (const float*)d_in[6];
    float* out = (float*)d_out;

    float *q, *k, *v, *o;
    cudaGetSymbolAddress((void**)&q, g_q);
    cudaGetSymbolAddress((void**)&k, g_k);
    cudaGetSymbolAddress((void**)&v, g_v);
    cudaGetSymbolAddress((void**)&o, g_o);

    cudaFuncSetAttribute(flash_mma,
                         cudaFuncAttributeMaxDynamicSharedMemorySize, FLASH_SMEM);

    dim3 blk(256);
    dim3 grid_proj(INNER / 128, ROWS / 128);   // (8, 32)

    // q = x @ Wq ; k,v = context @ Wkv (fp32 — precision-critical for q,k)
    sgemm128<<<grid_proj, blk>>>(x, Wq, q, ROWS, INNER, DMODEL, INNER, 0, nullptr);
    sgemm128<<<grid_proj, blk>>>(context, Wkv, k, ROWS, INNER, DMODEL, 2 * INNER, 0, nullptr);
    sgemm128<<<grid_proj, blk>>>(context, Wkv, v, ROWS, INNER, DMODEL, 2 * INNER, INNER, nullptr);

    // attention on tensor cores
    dim3 grid_attn(SEQ / 64, HEADS, BATCH);
    flash_mma<<<grid_attn, 128, FLASH_SMEM>>>(q, k, v, mask, o);

    // out = o @ Wout + bout
    sgemm128<<<grid_proj, blk>>>(o, Wout, out, ROWS, DMODEL, INNER, DMODEL, 0, bout);
}